// round 2
// baseline (speedup 1.0000x reference)
#include <cuda_runtime.h>
#include <cuda_bf16.h>
#include <math.h>

// Model dims
#define Bn 64
#define Sn 512
#define Tn 64
#define En 128
#define NHn 4
#define HDn 32
#define NLn 2
#define FFn 256
#define VOUTn 32000
#define TD (Tn-1)            // 63 decode steps
#define MROWS (Bn*Sn)        // 32768
#define DROWS (TD*Bn)        // 4032

// -------------------- packed f32x2 helpers --------------------
__device__ __forceinline__ unsigned long long pk(float x, float y) {
    unsigned long long r;
    asm("mov.b64 %0, {%1,%2};" : "=l"(r) : "f"(x), "f"(y));
    return r;
}
__device__ __forceinline__ void upk(unsigned long long v, float &x, float &y) {
    asm("mov.b64 {%0,%1}, %2;" : "=f"(x), "=f"(y) : "l"(v));
}
__device__ __forceinline__ void ffma2(unsigned long long &d, unsigned long long a, unsigned long long b) {
    asm("fma.rn.f32x2 %0, %1, %2, %0;" : "+l"(d) : "l"(a), "l"(b));
}
__device__ __forceinline__ unsigned long long mul2(unsigned long long a, unsigned long long b) {
    unsigned long long r;
    asm("mul.rn.f32x2 %0, %1, %2;" : "=l"(r) : "l"(a), "l"(b));
    return r;
}

// -------------------- scratch (device globals; no allocs allowed) --------------------
__device__ float g_x[MROWS*En];        // activations [B*S, E]
__device__ float g_qkv[MROWS*3*En];    // qkv [B*S, 384]
__device__ float g_ctx[MROWS*En];      // attention ctx / ff2 out
__device__ float g_ffh[MROWS*FFn];     // ff hidden / attn proj out
__device__ float g_h0[Bn*En];
__device__ float g_embx[DROWS*En];     // decoder input embeddings, row = t*64+b
__device__ float g_gatesx[DROWS*4*En]; // precomputed input gates
__device__ float g_hall[DROWS*En];     // all hidden states, row = t*64+b

// -------------------- embedding gathers --------------------
__global__ void gather_src_kernel(const int* __restrict__ src,
                                  const float* __restrict__ emb,
                                  float* __restrict__ out) {
    int n = blockIdx.x;                 // 0..32767 = b*512+s
    int tok = src[n];
    ((float4*)(out + (size_t)n*En))[threadIdx.x] =
        ((const float4*)(emb + (size_t)tok*En))[threadIdx.x];
}

__global__ void gather_trg_kernel(const int* __restrict__ trg,
                                  const float* __restrict__ emb,
                                  float* __restrict__ out) {
    int r = blockIdx.x;                 // r = t*64 + b
    int t = r >> 6, b = r & 63;
    int tok = trg[b*Tn + t];
    ((float4*)(out + (size_t)r*En))[threadIdx.x] =
        ((const float4*)(emb + (size_t)tok*En))[threadIdx.x];
}

// -------------------- fp32 GEMM: C[M,N] = A[M,K] @ B[N,K]^T + bias --------------------
// 128x128 tile, BK=16, 256 threads, 8x8 per-thread tile, f32x2 packed FMA,
// double-buffered smem with register prefetch. Requires N % 128 == 0.
#define GBM 128
#define GBN 128
#define GBK 16
#define GPAD 4   // smem row pad (floats) to reduce STS bank conflicts

template<int RELU, int PERMUTE>
__global__ __launch_bounds__(256)
void gemm_kernel(const float* __restrict__ A, const float* __restrict__ B,
                 const float* __restrict__ bias1, const float* __restrict__ bias2,
                 float* __restrict__ C, int M, int N, int K) {
    __shared__ __align__(16) float As[2][GBK][GBM + GPAD];
    __shared__ __align__(16) float Bs[2][GBK][GBN + GPAD];
    int tid = threadIdx.x;
    int tx = tid & 15, ty = tid >> 4;
    int rowBase = blockIdx.y * GBM;
    int colBase = blockIdx.x * GBN;

    // loader geometry: 512 float4 per matrix per tile; 2 per thread
    int lr = tid >> 2;             // 0..63, second pass +64
    int lc = (tid & 3) * 4;        // k-offset within 16

    unsigned long long acc2[8][4];
    #pragma unroll
    for (int i = 0; i < 8; i++)
        #pragma unroll
        for (int j = 0; j < 4; j++) acc2[i][j] = 0ull;

    float4 va[2], vb[2];
    int nsteps = K / GBK;

    // prefetch tile 0
    #pragma unroll
    for (int i = 0; i < 2; i++) {
        int r = lr + i*64;
        int gr = rowBase + r;
        va[i] = (gr < M) ? *(const float4*)(A + (size_t)gr*K + lc)
                         : make_float4(0.f,0.f,0.f,0.f);
        vb[i] = *(const float4*)(B + (size_t)(colBase + r)*K + lc);
    }
    #pragma unroll
    for (int i = 0; i < 2; i++) {
        int r = lr + i*64;
        As[0][lc+0][r]=va[i].x; As[0][lc+1][r]=va[i].y; As[0][lc+2][r]=va[i].z; As[0][lc+3][r]=va[i].w;
        Bs[0][lc+0][r]=vb[i].x; Bs[0][lc+1][r]=vb[i].y; Bs[0][lc+2][r]=vb[i].z; Bs[0][lc+3][r]=vb[i].w;
    }
    __syncthreads();

    for (int s = 0; s < nsteps; s++) {
        if (s + 1 < nsteps) {
            int k0 = (s+1)*GBK;
            #pragma unroll
            for (int i = 0; i < 2; i++) {
                int r = lr + i*64;
                int gr = rowBase + r;
                va[i] = (gr < M) ? *(const float4*)(A + (size_t)gr*K + k0 + lc)
                                 : make_float4(0.f,0.f,0.f,0.f);
                vb[i] = *(const float4*)(B + (size_t)(colBase + r)*K + k0 + lc);
            }
        }
        int buf = s & 1;
        #pragma unroll
        for (int kk = 0; kk < GBK; kk++) {
            float a[8], b[8];
            *(float4*)&a[0] = *(const float4*)&As[buf][kk][ty*8];
            *(float4*)&a[4] = *(const float4*)&As[buf][kk][ty*8+4];
            *(float4*)&b[0] = *(const float4*)&Bs[buf][kk][tx*8];
            *(float4*)&b[4] = *(const float4*)&Bs[buf][kk][tx*8+4];
            unsigned long long bp[4], ap[8];
            #pragma unroll
            for (int j2 = 0; j2 < 4; j2++) bp[j2] = pk(b[2*j2], b[2*j2+1]);
            #pragma unroll
            for (int i = 0; i < 8; i++) ap[i] = pk(a[i], a[i]);
            #pragma unroll
            for (int i = 0; i < 8; i++)
                #pragma unroll
                for (int j2 = 0; j2 < 4; j2++)
                    ffma2(acc2[i][j2], ap[i], bp[j2]);
        }
        if (s + 1 < nsteps) {
            int nb = (s+1) & 1;
            #pragma unroll
            for (int i = 0; i < 2; i++) {
                int r = lr + i*64;
                As[nb][lc+0][r]=va[i].x; As[nb][lc+1][r]=va[i].y; As[nb][lc+2][r]=va[i].z; As[nb][lc+3][r]=va[i].w;
                Bs[nb][lc+0][r]=vb[i].x; Bs[nb][lc+1][r]=vb[i].y; Bs[nb][lc+2][r]=vb[i].z; Bs[nb][lc+3][r]=vb[i].w;
            }
        }
        __syncthreads();
    }

    // epilogue
    #pragma unroll
    for (int i = 0; i < 8; i++) {
        int row = rowBase + ty*8 + i;
        if (row < M) {
            float cv[8];
            #pragma unroll
            for (int j2 = 0; j2 < 4; j2++) upk(acc2[i][j2], cv[2*j2], cv[2*j2+1]);
            #pragma unroll
            for (int j4 = 0; j4 < 2; j4++) {
                float4 v;
                float* vp = &v.x;
                #pragma unroll
                for (int j = 0; j < 4; j++) {
                    int col = colBase + tx*8 + j4*4 + j;
                    float val = cv[j4*4 + j];
                    if (bias1) val += bias1[col];
                    if (bias2) val += bias2[col];
                    if (RELU) val = fmaxf(val, 0.f);
                    vp[j] = val;
                }
                size_t off;
                if (PERMUTE) {
                    int t = row >> 6, b = row & 63;
                    off = ((size_t)(b*TD + t))*N + colBase + tx*8 + j4*4;
                } else {
                    off = (size_t)row*N + colBase + tx*8 + j4*4;
                }
                *(float4*)(C + off) = v;
            }
        }
    }
}

// -------------------- fused flash-style attention (f32x2 packed) --------------------
// grid = B*NH*(S/128) = 1024 blocks, 128 threads, one thread per query row.
__global__ __launch_bounds__(128)
void attn_kernel(const float* __restrict__ qkv, float* __restrict__ ctx) {
    int blk = blockIdx.x;
    int qc = blk & 3;
    int h  = (blk >> 2) & 3;
    int b  = blk >> 4;
    int qi = qc*128 + threadIdx.x;
    const float* base = qkv + ((size_t)b*Sn)*(3*En);

    unsigned long long q2[16];
    {
        const float4* qp = (const float4*)(base + (size_t)qi*(3*En) + h*HDn);
        #pragma unroll
        for (int i = 0; i < 8; i++) {
            float4 v = qp[i];
            q2[2*i]   = pk(v.x, v.y);
            q2[2*i+1] = pk(v.z, v.w);
        }
    }

    __shared__ __align__(16) float Ks[64][32];
    __shared__ __align__(16) float Vs[64][32];

    float m = -1e30f, l = 0.f;
    unsigned long long acc2[16];
    #pragma unroll
    for (int d = 0; d < 16; d++) acc2[d] = 0ull;

    const float scale = 0.17677669529663689f;  // 1/sqrt(32)

    for (int s0 = 0; s0 < Sn; s0 += 64) {
        __syncthreads();
        for (int i = threadIdx.x; i < 64*8; i += 128) {
            int r = i >> 3, c4 = (i & 7) * 4;
            const float* rowp = base + (size_t)(s0 + r)*(3*En) + h*HDn;
            *(float4*)&Ks[r][c4] = *(const float4*)(rowp + En   + c4);
            *(float4*)&Vs[r][c4] = *(const float4*)(rowp + 2*En + c4);
        }
        __syncthreads();
        #pragma unroll 2
        for (int j = 0; j < 64; j++) {
            const ulonglong2* kp = (const ulonglong2*)&Ks[j][0];
            unsigned long long sd = 0ull;
            #pragma unroll
            for (int d4 = 0; d4 < 8; d4++) {
                ulonglong2 kk2 = kp[d4];
                ffma2(sd, q2[2*d4],   kk2.x);
                ffma2(sd, q2[2*d4+1], kk2.y);
            }
            float lo, hi;
            upk(sd, lo, hi);
            float s = (lo + hi) * scale;
            if (s > m) {
                float corr = __expf(m - s);
                m = s; l *= corr;
                unsigned long long cp = pk(corr, corr);
                #pragma unroll
                for (int d = 0; d < 16; d++) acc2[d] = mul2(acc2[d], cp);
            }
            float p = __expf(s - m);
            l += p;
            unsigned long long pp = pk(p, p);
            const ulonglong2* vp = (const ulonglong2*)&Vs[j][0];
            #pragma unroll
            for (int d4 = 0; d4 < 8; d4++) {
                ulonglong2 vv = vp[d4];
                ffma2(acc2[2*d4],   pp, vv.x);
                ffma2(acc2[2*d4+1], pp, vv.y);
            }
        }
    }
    float inv = 1.f / l;
    float* op = ctx + ((size_t)(b*Sn + qi))*En + h*HDn;
    #pragma unroll
    for (int i = 0; i < 8; i++) {
        float a0,a1,a2,a3;
        upk(acc2[2*i],   a0, a1);
        upk(acc2[2*i+1], a2, a3);
        ((float4*)op)[i] = make_float4(a0*inv, a1*inv, a2*inv, a3*inv);
    }
}

// -------------------- residual add + layernorm (in-place on x) --------------------
__global__ __launch_bounds__(128)
void add_ln_kernel(float* __restrict__ x, const float* __restrict__ y,
                   const float* __restrict__ w, const float* __restrict__ bb) {
    int r = blockIdx.x, e = threadIdx.x;
    size_t idx = (size_t)r*En + e;
    float v = x[idx] + y[idx];

    __shared__ float red[4];
    float s = v;
    #pragma unroll
    for (int o = 16; o; o >>= 1) s += __shfl_xor_sync(0xffffffffu, s, o);
    if ((e & 31) == 0) red[e >> 5] = s;
    __syncthreads();
    float mu = (red[0]+red[1]+red[2]+red[3]) * (1.f/En);
    __syncthreads();
    float d = v - mu;
    s = d*d;
    #pragma unroll
    for (int o = 16; o; o >>= 1) s += __shfl_xor_sync(0xffffffffu, s, o);
    if ((e & 31) == 0) red[e >> 5] = s;
    __syncthreads();
    float var = (red[0]+red[1]+red[2]+red[3]) * (1.f/En);
    x[idx] = d * rsqrtf(var + 1e-5f) * w[e] + bb[e];
}

// -------------------- h0 = mean over S --------------------
__global__ __launch_bounds__(128)
void mean_kernel(const float* __restrict__ x, float* __restrict__ h0) {
    int b = blockIdx.x, e = threadIdx.x;
    float s = 0.f;
    for (int i = 0; i < Sn; i++) s += x[((size_t)b*Sn + i)*En + e];
    h0[b*En + e] = s * (1.f/Sn);
}

// -------------------- LSTM recurrence: one block per batch element --------------------
__device__ __forceinline__ float sigf(float x) { return 1.f / (1.f + __expf(-x)); }

__global__ __launch_bounds__(512)
void lstm_kernel(const float* __restrict__ gatesx, const float* __restrict__ w_hh,
                 const float* __restrict__ h0, float* __restrict__ hall) {
    __shared__ __align__(16) float hs[En];
    __shared__ float cs[En];
    __shared__ float gsm[4*En];
    int b = blockIdx.x;
    int k = threadIdx.x;           // gate index 0..511
    if (k < En) { hs[k] = h0[b*En + k]; cs[k] = 0.f; }
    __syncthreads();

    const ulonglong2* wrow = (const ulonglong2*)(w_hh + (size_t)k*En);
    const ulonglong2* h2p  = (const ulonglong2*)hs;

    for (int t = 0; t < TD; t++) {
        const float* gx = gatesx + ((size_t)(t*Bn + b))*(4*En);
        unsigned long long accp = 0ull;
        #pragma unroll
        for (int e4 = 0; e4 < En/4; e4++) {
            ulonglong2 w4 = wrow[e4];
            ulonglong2 h4 = h2p[e4];
            ffma2(accp, w4.x, h4.x);
            ffma2(accp, w4.y, h4.y);
        }
        float lo, hi;
        upk(accp, lo, hi);
        gsm[k] = gx[k] + lo + hi;
        __syncthreads();
        if (k < En) {
            float gi = gsm[k], gf = gsm[En+k], gg = gsm[2*En+k], go = gsm[3*En+k];
            float c = sigf(gf)*cs[k] + sigf(gi)*tanhf(gg);
            float h = sigf(go)*tanhf(c);
            cs[k] = c; hs[k] = h;
            hall[((size_t)(t*Bn + b))*En + k] = h;
        }
        __syncthreads();
    }
}

// -------------------- host launcher --------------------
extern "C" void kernel_launch(void* const* d_in, const int* in_sizes, int n_in,
                              void* d_out, int out_size) {
    const int*   src     = (const int*)  d_in[0];
    const int*   trg     = (const int*)  d_in[1];
    const float* emb_in  = (const float*)d_in[2];
    const float* emb_out = (const float*)d_in[3];
    const float* wqkv    = (const float*)d_in[4];
    const float* bqkv    = (const float*)d_in[5];
    const float* wo      = (const float*)d_in[6];
    const float* bo      = (const float*)d_in[7];
    const float* ln1w    = (const float*)d_in[8];
    const float* ln1b    = (const float*)d_in[9];
    const float* w1      = (const float*)d_in[10];
    const float* b1      = (const float*)d_in[11];
    const float* w2      = (const float*)d_in[12];
    const float* b2      = (const float*)d_in[13];
    const float* ln2w    = (const float*)d_in[14];
    const float* ln2b    = (const float*)d_in[15];
    const float* w_ih    = (const float*)d_in[16];
    const float* w_hh    = (const float*)d_in[17];
    const float* b_ih    = (const float*)d_in[18];
    const float* b_hh    = (const float*)d_in[19];
    const float* fc_w    = (const float*)d_in[20];
    const float* fc_b    = (const float*)d_in[21];
    float* out = (float*)d_out;

    float *x, *qkv, *ctx, *ffh, *h0, *embx, *gatesx, *hall;
    cudaGetSymbolAddress((void**)&x,      g_x);
    cudaGetSymbolAddress((void**)&qkv,    g_qkv);
    cudaGetSymbolAddress((void**)&ctx,    g_ctx);
    cudaGetSymbolAddress((void**)&ffh,    g_ffh);
    cudaGetSymbolAddress((void**)&h0,     g_h0);
    cudaGetSymbolAddress((void**)&embx,   g_embx);
    cudaGetSymbolAddress((void**)&gatesx, g_gatesx);
    cudaGetSymbolAddress((void**)&hall,   g_hall);

    // 1) embed src
    gather_src_kernel<<<MROWS, 32>>>(src, emb_in, x);

    // 2) encoder layers
    for (int l = 0; l < NLn; l++) {
        gemm_kernel<0,0><<<dim3(3*En/GBN, MROWS/GBM), 256>>>(
            x, wqkv + (size_t)l*3*En*En, bqkv + l*3*En, nullptr, qkv, MROWS, 3*En, En);
        attn_kernel<<<Bn*NHn*(Sn/128), 128>>>(qkv, ctx);
        gemm_kernel<0,0><<<dim3(En/GBN, MROWS/GBM), 256>>>(
            ctx, wo + (size_t)l*En*En, bo + l*En, nullptr, ffh, MROWS, En, En);
        add_ln_kernel<<<MROWS, 128>>>(x, ffh, ln1w + l*En, ln1b + l*En);
        gemm_kernel<1,0><<<dim3(FFn/GBN, MROWS/GBM), 256>>>(
            x, w1 + (size_t)l*FFn*En, b1 + l*FFn, nullptr, ffh, MROWS, FFn, En);
        gemm_kernel<0,0><<<dim3(En/GBN, MROWS/GBM), 256>>>(
            ffh, w2 + (size_t)l*En*FFn, b2 + l*En, nullptr, ctx, MROWS, En, FFn);
        add_ln_kernel<<<MROWS, 128>>>(x, ctx, ln2w + l*En, ln2b + l*En);
    }

    // 3) h0 = mean over S
    mean_kernel<<<Bn, 128>>>(x, h0);

    // 4) decoder input-side precompute
    gather_trg_kernel<<<DROWS, 32>>>(trg, emb_out, embx);
    gemm_kernel<0,0><<<dim3(4*En/GBN, (DROWS + GBM - 1)/GBM), 256>>>(
        embx, w_ih, b_ih, b_hh, gatesx, DROWS, 4*En, En);

    // 5) LSTM recurrence (parallel over batch)
    lstm_kernel<<<Bn, 512>>>(gatesx, w_hh, h0, hall);

    // 6) logits = hall @ fc_w^T + fc_b, permuted to [B, T-1, V]
    gemm_kernel<0,1><<<dim3(VOUTn/GBN, (DROWS + GBM - 1)/GBM), 256>>>(
        hall, fc_w, fc_b, nullptr, out, DROWS, VOUTn, En);
}